// round 6
// baseline (speedup 1.0000x reference)
#include <cuda_runtime.h>

#define DEPTH   15
#define HDIM    128
#define XDIM    128
#define K2      256
#define NNODES  ((1 << DEPTH) - 1)
#define LEAVES  (1 << (DEPTH - 1))
#define KT      16

__device__ __forceinline__ unsigned long long pk2(float x, float y) {
    unsigned long long r;
    asm("mov.b64 %0, {%1, %2};" : "=l"(r) : "f"(x), "f"(y));
    return r;
}
__device__ __forceinline__ void upk2(unsigned long long v, float& x, float& y) {
    asm("mov.b64 {%0, %1}, %2;" : "=f"(x), "=f"(y) : "l"(v));
}
__device__ __forceinline__ void fma2(unsigned long long& c, unsigned long long a,
                                     unsigned long long b) {
    asm("fma.rn.f32x2 %0, %1, %2, %0;" : "+l"(c) : "l"(a), "l"(b));
}
__device__ __forceinline__ float sigf(float x)      { return 1.0f / (1.0f + __expf(-x)); }
__device__ __forceinline__ float tanh_fast(float x) { return 2.0f / (1.0f + __expf(-2.0f * x)) - 1.0f; }

__device__ __forceinline__ void cpa16(float* dst, const float* src) {
    unsigned d = (unsigned)__cvta_generic_to_shared(dst);
    asm volatile("cp.async.ca.shared.global [%0], [%1], 16;" :: "r"(d), "l"(src));
}
#define CP_COMMIT() asm volatile("cp.async.commit_group;")
#define CP_WAIT0()  asm volatile("cp.async.wait_group 0;" ::: "memory")

// ---------------- leaf: h_leaf = (1-sig(a_lo))*tanh(a_hi), a = x@Ww + Wb ----
__global__ void __launch_bounds__(256, 1)
leaf_kernel(float* __restrict__ h, const float* __restrict__ x,
            const float* __restrict__ Ww, const float* __restrict__ Wb, int R)
{
    extern __shared__ float sm[];
    float* xs = sm;                 // 64*128
    float* as = sm + 64 * XDIM;     // 64*256
    float* ws = as + 64 * K2;       // 2*16*256
    const int tid = threadIdx.x;
    const int rbase = blockIdx.x * 64;

    #pragma unroll
    for (int j = 0; j < 4; j++) cpa16(ws + tid * 4 + j * 1024, Ww + tid * 4 + j * 1024);
    CP_COMMIT();

    for (int idx = tid; idx < 64 * 32; idx += 256) {
        int r = idx >> 5, seg = idx & 31, rg = rbase + r;
        float4 v = make_float4(0.f, 0.f, 0.f, 0.f);
        if (rg < R) {
            int b = rg >> (DEPTH - 1), leaf = rg & (LEAVES - 1);
            v = *(const float4*)(x + ((size_t)b * NNODES + (LEAVES - 1) + leaf) * XDIM + seg * 4);
        }
        *(float4*)(xs + r * XDIM + seg * 4) = v;
    }

    const int tx = tid & 31, ty = tid >> 5;
    unsigned long long acc[8][4];
    #pragma unroll
    for (int r = 0; r < 8; r++)
        #pragma unroll
        for (int c = 0; c < 4; c++) acc[r][c] = 0ULL;

    for (int kt = 0; kt < XDIM / KT; kt++) {
        CP_WAIT0();
        __syncthreads();
        if (kt + 1 < XDIM / KT) {
            const float* src = Ww + (kt + 1) * KT * K2;
            float* dst = ws + ((kt + 1) & 1) * (KT * K2);
            #pragma unroll
            for (int j = 0; j < 4; j++) cpa16(dst + tid * 4 + j * 1024, src + tid * 4 + j * 1024);
            CP_COMMIT();
        }
        const float* w = ws + (kt & 1) * (KT * K2);
        #pragma unroll
        for (int k = 0; k < KT; k++) {
            unsigned long long w0 = *(const unsigned long long*)(w + k * K2 + tx * 8);
            unsigned long long w1 = *(const unsigned long long*)(w + k * K2 + tx * 8 + 2);
            unsigned long long w2 = *(const unsigned long long*)(w + k * K2 + tx * 8 + 4);
            unsigned long long w3 = *(const unsigned long long*)(w + k * K2 + tx * 8 + 6);
            #pragma unroll
            for (int r = 0; r < 8; r++) {
                float a = xs[(ty * 8 + r) * XDIM + kt * KT + k];
                unsigned long long aa = pk2(a, a);
                fma2(acc[r][0], aa, w0); fma2(acc[r][1], aa, w1);
                fma2(acc[r][2], aa, w2); fma2(acc[r][3], aa, w3);
            }
        }
    }

    float bias[8];
    #pragma unroll
    for (int c = 0; c < 8; c++) bias[c] = Wb[tx * 8 + c];
    #pragma unroll
    for (int r = 0; r < 8; r++) {
        float v[8];
        #pragma unroll
        for (int c = 0; c < 4; c++) upk2(acc[r][c], v[2 * c], v[2 * c + 1]);
        float4* p = (float4*)(as + (ty * 8 + r) * K2 + tx * 8);
        p[0] = make_float4(v[0] + bias[0], v[1] + bias[1], v[2] + bias[2], v[3] + bias[3]);
        p[1] = make_float4(v[4] + bias[4], v[5] + bias[5], v[6] + bias[6], v[7] + bias[7]);
    }
    __syncthreads();

    for (int idx = tid; idx < 64 * 32; idx += 256) {
        int r = idx >> 5, seg = idx & 31, rg = rbase + r;
        if (rg >= R) continue;
        float4 a1 = *(const float4*)(as + r * K2 + seg * 4);
        float4 a2 = *(const float4*)(as + r * K2 + HDIM + seg * 4);
        float4 o;
        o.x = (1.f - sigf(a1.x)) * tanh_fast(a2.x);
        o.y = (1.f - sigf(a1.y)) * tanh_fast(a2.y);
        o.z = (1.f - sigf(a1.z)) * tanh_fast(a2.z);
        o.w = (1.f - sigf(a1.w)) * tanh_fast(a2.w);
        int b = rg >> (DEPTH - 1), leaf = rg & (LEAVES - 1);
        *(float4*)(h + ((size_t)b * NNODES + (LEAVES - 1) + leaf) * HDIM + seg * 4) = o;
    }
}

// ---------------- one tree level (fused f-GEMM + cand-GEMM + combine) -------
template<int BM>
__global__ void __launch_bounds__(256, 1)
level_kernel(float* __restrict__ h,
             const float* __restrict__ Ufw, const float* __restrict__ Ufb,
             const float* __restrict__ Uhw, const float* __restrict__ Uhb,
             int l, int R)
{
    const int cnt = 1 << l, start = cnt - 1;
    extern __shared__ float sm[];
    float* hcs = sm;                 // BM*256
    float* fs  = sm + BM * K2;       // BM*256
    float* ws  = sm + 2 * BM * K2;   // 2*16*256
    const int tid = threadIdx.x;
    const int rbase = blockIdx.x * BM;

    #pragma unroll
    for (int j = 0; j < 4; j++) cpa16(ws + tid * 4 + j * 1024, Ufw + tid * 4 + j * 1024);
    CP_COMMIT();

    for (int idx = tid; idx < BM * 64; idx += 256) {
        int r = idx >> 6, seg = idx & 63, rg = rbase + r;
        float4 v = make_float4(0.f, 0.f, 0.f, 0.f);
        if (rg < R) {
            int b = rg >> l, i = rg & (cnt - 1);
            v = *(const float4*)(h + ((size_t)b * NNODES + (size_t)2 * (start + i) + 1) * HDIM + seg * 4);
        }
        *(float4*)(hcs + r * K2 + seg * 4) = v;
    }

    // phase 1: f = sigmoid(hc @ Ufw + Ufb)
    {
        const int tx = tid & 31, ty = tid >> 5;
        constexpr int TM = BM / 8;
        unsigned long long acc[TM][4];
        #pragma unroll
        for (int r = 0; r < TM; r++)
            #pragma unroll
            for (int c = 0; c < 4; c++) acc[r][c] = 0ULL;

        for (int kt = 0; kt < K2 / KT; kt++) {
            CP_WAIT0();
            __syncthreads();
            if (kt + 1 < K2 / KT) {
                const float* src = Ufw + (kt + 1) * KT * K2;
                float* dst = ws + ((kt + 1) & 1) * (KT * K2);
                #pragma unroll
                for (int j = 0; j < 4; j++) cpa16(dst + tid * 4 + j * 1024, src + tid * 4 + j * 1024);
                CP_COMMIT();
            }
            const float* w = ws + (kt & 1) * (KT * K2);
            #pragma unroll
            for (int k = 0; k < KT; k++) {
                unsigned long long w0 = *(const unsigned long long*)(w + k * K2 + tx * 8);
                unsigned long long w1 = *(const unsigned long long*)(w + k * K2 + tx * 8 + 2);
                unsigned long long w2 = *(const unsigned long long*)(w + k * K2 + tx * 8 + 4);
                unsigned long long w3 = *(const unsigned long long*)(w + k * K2 + tx * 8 + 6);
                #pragma unroll
                for (int r = 0; r < TM; r++) {
                    float a = hcs[(ty * TM + r) * K2 + kt * KT + k];
                    unsigned long long aa = pk2(a, a);
                    fma2(acc[r][0], aa, w0); fma2(acc[r][1], aa, w1);
                    fma2(acc[r][2], aa, w2); fma2(acc[r][3], aa, w3);
                }
            }
        }
        __syncthreads();

        // prefetch Uhw tile 0 (overlaps epilogue)
        #pragma unroll
        for (int j = 0; j < 2; j++) cpa16(ws + tid * 4 + j * 1024, Uhw + tid * 4 + j * 1024);
        CP_COMMIT();

        float bias[8];
        #pragma unroll
        for (int c = 0; c < 8; c++) bias[c] = Ufb[tx * 8 + c];
        #pragma unroll
        for (int r = 0; r < TM; r++) {
            float v[8];
            #pragma unroll
            for (int c = 0; c < 4; c++) upk2(acc[r][c], v[2 * c], v[2 * c + 1]);
            #pragma unroll
            for (int c = 0; c < 8; c++) v[c] = sigf(v[c] + bias[c]);
            float4* p = (float4*)(fs + (ty * TM + r) * K2 + tx * 8);
            p[0] = make_float4(v[0], v[1], v[2], v[3]);
            p[1] = make_float4(v[4], v[5], v[6], v[7]);
        }
    }

    // phase 2: cand = tanh((f*hc) @ Uhw + Uhb); combine; store
    {
        const int tx = tid & 15, ty = tid >> 4;
        constexpr int TM2 = BM / 16;
        unsigned long long acc[TM2][4];
        #pragma unroll
        for (int r = 0; r < TM2; r++)
            #pragma unroll
            for (int c = 0; c < 4; c++) acc[r][c] = 0ULL;

        for (int kt = 0; kt < K2 / KT; kt++) {
            CP_WAIT0();
            __syncthreads();
            if (kt + 1 < K2 / KT) {
                const float* src = Uhw + (kt + 1) * KT * HDIM;
                float* dst = ws + ((kt + 1) & 1) * (KT * HDIM);
                #pragma unroll
                for (int j = 0; j < 2; j++) cpa16(dst + tid * 4 + j * 1024, src + tid * 4 + j * 1024);
                CP_COMMIT();
            }
            const float* w = ws + (kt & 1) * (KT * HDIM);
            #pragma unroll
            for (int k = 0; k < KT; k++) {
                unsigned long long w0 = *(const unsigned long long*)(w + k * HDIM + tx * 8);
                unsigned long long w1 = *(const unsigned long long*)(w + k * HDIM + tx * 8 + 2);
                unsigned long long w2 = *(const unsigned long long*)(w + k * HDIM + tx * 8 + 4);
                unsigned long long w3 = *(const unsigned long long*)(w + k * HDIM + tx * 8 + 6);
                #pragma unroll
                for (int r = 0; r < TM2; r++) {
                    int row = ty * TM2 + r, kk = kt * KT + k;
                    float a = fs[row * K2 + kk] * hcs[row * K2 + kk];
                    unsigned long long aa = pk2(a, a);
                    fma2(acc[r][0], aa, w0); fma2(acc[r][1], aa, w1);
                    fma2(acc[r][2], aa, w2); fma2(acc[r][3], aa, w3);
                }
            }
        }

        float bias[8];
        #pragma unroll
        for (int c = 0; c < 8; c++) bias[c] = Uhb[tx * 8 + c];
        #pragma unroll
        for (int r = 0; r < TM2; r++) {
            int row = ty * TM2 + r, rg = rbase + row;
            if (rg >= R) continue;
            float v[8];
            #pragma unroll
            for (int c = 0; c < 4; c++) upk2(acc[r][c], v[2 * c], v[2 * c + 1]);
            #pragma unroll
            for (int c = 0; c < 8; c++) {
                int col = tx * 8 + c;
                float cand = tanh_fast(v[c] + bias[c]);
                float f1 = fs[row * K2 + col], f2 = fs[row * K2 + col + HDIM];
                float h1 = hcs[row * K2 + col], h2 = hcs[row * K2 + col + HDIM];
                v[c] = (1.f - f1 - f2) * cand + f1 * h1 + f2 * h2;
            }
            int b = rg >> l, i = rg & (cnt - 1);
            float* dst = h + ((size_t)b * NNODES + start + i) * HDIM + tx * 8;
            ((float4*)dst)[0] = make_float4(v[0], v[1], v[2], v[3]);
            ((float4*)dst)[1] = make_float4(v[4], v[5], v[6], v[7]);
        }
    }
}

extern "C" void kernel_launch(void* const* d_in, const int* in_sizes, int n_in,
                              void* d_out, int out_size)
{
    const float* x   = (const float*)d_in[0];
    const float* Ww  = (const float*)d_in[1];
    const float* Wb  = (const float*)d_in[2];
    const float* Ufw = (const float*)d_in[3];
    const float* Ufb = (const float*)d_in[4];
    const float* Uhw = (const float*)d_in[5];
    const float* Uhb = (const float*)d_in[6];
    float* h = (float*)d_out;

    const int Btot = (out_size / HDIM) / NNODES;

    const int smem_leaf = (64 * XDIM + 64 * K2 + 2 * KT * K2) * (int)sizeof(float);
    const int smem_l64  = (2 * 64 * K2 + 2 * KT * K2) * (int)sizeof(float);
    const int smem_l16  = (2 * 16 * K2 + 2 * KT * K2) * (int)sizeof(float);

    static bool attr_done = false;
    if (!attr_done) {
        cudaFuncSetAttribute(leaf_kernel,      cudaFuncAttributeMaxDynamicSharedMemorySize, smem_leaf);
        cudaFuncSetAttribute(level_kernel<64>, cudaFuncAttributeMaxDynamicSharedMemorySize, smem_l64);
        cudaFuncSetAttribute(level_kernel<16>, cudaFuncAttributeMaxDynamicSharedMemorySize, smem_l16);
        attr_done = true;
    }

    const int Rleaf = Btot * LEAVES;
    leaf_kernel<<<(Rleaf + 63) / 64, 256, smem_leaf>>>(h, x, Ww, Wb, Rleaf);

    for (int l = DEPTH - 2; l >= 0; l--) {
        int R = Btot << l;
        if (R >= 64)
            level_kernel<64><<<(R + 63) / 64, 256, smem_l64>>>(h, Ufw, Ufb, Uhw, Uhb, l, R);
        else
            level_kernel<16><<<(R + 15) / 16, 256, smem_l16>>>(h, Ufw, Ufb, Uhw, Uhb, l, R);
    }
}